// round 6
// baseline (speedup 1.0000x reference)
#include <cuda_runtime.h>
#include <cuda_bf16.h>

#define SPL_EPS 1e-12f
#define NKNOTS 30
#define NSEG   29

// PCHIP spline, uniform knots. Per segment: y = c0 + t*(c1 + t*(c2 + t*c3)).
// The 29 segments' coefficients live one-per-lane in registers; the per-element
// gather is done with __shfl_sync (no shared-memory / L1tex traffic).
__global__ void __launch_bounds__(256)
spline_eval_kernel(const float* __restrict__ x,
                   const float* __restrict__ knots,
                   const float* __restrict__ coeffs,
                   float* __restrict__ out,
                   int n)
{
    __shared__ float  s_k[NKNOTS];
    __shared__ float  s_y[NKNOTS];
    __shared__ float  s_h[NSEG];
    __shared__ float  s_delta[NSEG];
    __shared__ float  s_d[NKNOTS];
    __shared__ float4 s_c[NSEG];
    __shared__ float  s_scal[3];   // k0, kN, invH

    const int tid  = threadIdx.x;
    const int lane = tid & 31;

    // ---- tiny PCHIP prep, redundantly per block ----
    if (tid < NKNOTS) {
        s_k[tid] = knots[tid];
        s_y[tid] = coeffs[tid];
    }
    __syncthreads();
    if (tid < NSEG) {
        float h = s_k[tid + 1] - s_k[tid];
        s_h[tid]     = h;
        s_delta[tid] = (s_y[tid + 1] - s_y[tid]) / (h + SPL_EPS);
    }
    __syncthreads();
    if (tid < NKNOTS) {
        float d;
        if (tid == 0) {
            float h0 = s_h[0], h1 = s_h[1];
            float de0 = s_delta[0], de1 = s_delta[1];
            d = ((2.0f * h0 + h1) * de0 - h0 * de1) / (h0 + h1 + SPL_EPS);
            if (d * de0 <= 0.0f)                 d = 0.0f;
            else if (fabsf(d) > 3.0f * fabsf(de0)) d = 3.0f * de0;
        } else if (tid == NKNOTS - 1) {
            float hl = s_h[NSEG - 1], hp = s_h[NSEG - 2];
            float del = s_delta[NSEG - 1], dep = s_delta[NSEG - 2];
            d = ((2.0f * hl + hp) * del - hl * dep) / (hl + hp + SPL_EPS);
            if (d * del <= 0.0f)                 d = 0.0f;
            else if (fabsf(d) > 3.0f * fabsf(del)) d = 3.0f * del;
        } else {
            float hkm1 = s_h[tid - 1], hk = s_h[tid];
            float dm = s_delta[tid - 1], dp = s_delta[tid];
            float w1 = 2.0f * hk + hkm1;
            float w2 = hk + 2.0f * hkm1;
            float dint = (w1 + w2) / (w1 / (dm + SPL_EPS) + w2 / (dp + SPL_EPS));
            d = (dm * dp > 0.0f) ? dint : 0.0f;
        }
        s_d[tid] = d;
    }
    __syncthreads();
    if (tid < NSEG) {
        float h      = s_h[tid];
        float safe_h = (fabsf(h) < SPL_EPS) ? 1.0f : h;
        float yk  = s_y[tid], yk1 = s_y[tid + 1];
        float hd0 = safe_h * s_d[tid];
        float hd1 = safe_h * s_d[tid + 1];
        float4 c;
        c.x = yk;
        c.y = hd0;
        c.z = -3.0f * yk - 2.0f * hd0 + 3.0f * yk1 - hd1;
        c.w =  2.0f * yk +        hd0 - 2.0f * yk1 + hd1;
        s_c[tid] = c;
    }
    if (tid == 0) {
        float k0 = s_k[0];
        float kN = s_k[NKNOTS - 1];
        s_scal[0] = k0;
        s_scal[1] = kN;
        // knots are linspace -> uniform segment width.
        s_scal[2] = (float)(NKNOTS - 1) / (kN - k0);
    }
    __syncthreads();

    const float k0   = s_scal[0];
    const float kN   = s_scal[1];
    const float invH = s_scal[2];

    // Each lane holds one segment's coefficients in registers.
    const int sl = lane < NSEG ? lane : (NSEG - 1);
    const float4 cc = s_c[sl];
    const float rc0 = cc.x, rc1 = cc.y, rc2 = cc.z, rc3 = cc.w;

    // ---- streaming evaluation, float4 vectorized, warp-uniform loop ----
    const int n4 = n >> 2;
    const float4* __restrict__ x4 = (const float4*)x;
    float4* __restrict__ o4 = (float4*)out;

    const int warp_global = (blockIdx.x * blockDim.x + tid) >> 5;
    const int num_warps   = (gridDim.x * blockDim.x) >> 5;
    const int stride      = num_warps << 5;

    auto eval1 = [&](float xv) -> float {
        float xc = fminf(fmaxf(xv, k0), kN);
        float s  = (xc - k0) * invH;
        int idx  = (int)s;
        idx = idx < 0 ? 0 : (idx > NSEG - 1 ? NSEG - 1 : idx);
        float t  = s - (float)idx;
        float c0 = __shfl_sync(0xffffffffu, rc0, idx);
        float c1 = __shfl_sync(0xffffffffu, rc1, idx);
        float c2 = __shfl_sync(0xffffffffu, rc2, idx);
        float c3 = __shfl_sync(0xffffffffu, rc3, idx);
        return fmaf(t, fmaf(t, fmaf(t, c3, c2), c1), c0);
    };

    for (int ib = warp_global << 5; ib < n4; ib += stride) {
        int i = ib + lane;
        bool act = (i < n4);
        float4 xv = act ? x4[i] : make_float4(0.f, 0.f, 0.f, 0.f);
        float4 yv;
        yv.x = eval1(xv.x);
        yv.y = eval1(xv.y);
        yv.z = eval1(xv.z);
        yv.w = eval1(xv.w);
        if (act) o4[i] = yv;
    }

    // scalar tail (n not divisible by 4), warp-uniform as well
    const int tail_start = n4 << 2;
    for (int ib = tail_start + (warp_global << 5); ib < n; ib += stride) {
        int i = ib + lane;
        bool act = (i < n);
        float xv = act ? x[i] : 0.f;
        float yv = eval1(xv);
        if (act) out[i] = yv;
    }
}

extern "C" void kernel_launch(void* const* d_in, const int* in_sizes, int n_in,
                              void* d_out, int out_size)
{
    const float* x      = (const float*)d_in[0];
    const float* knots  = (const float*)d_in[1];
    const float* coeffs = (const float*)d_in[2];
    float* out          = (float*)d_out;
    const int n         = in_sizes[0];

    const int threads = 256;
    int blocks = 148 * 8;
    int work4  = (n >> 2);
    if (work4 > 0) {
        int need = (work4 + threads - 1) / threads;
        if (blocks > need) blocks = need;
    }
    if (blocks < 1) blocks = 1;

    spline_eval_kernel<<<blocks, threads>>>(x, knots, coeffs, out, n);
}

// round 7
// speedup vs baseline: 1.0775x; 1.0775x over previous
#include <cuda_runtime.h>
#include <cuda_bf16.h>

#define SPL_EPS 1e-12f
#define NKNOTS 30
#define NSEG   29

// PCHIP spline, uniform knots. Per segment: y = c0 + t*(c1 + t*(c2 + t*c3)).
// The 29 segments' float4 coefficients are replicated per-lane in shared memory
// (s_crep[seg][lane]) so the per-element LDS.128 gather is bank-conflict-free
// for ANY index pattern: lane l's 16B slot starts at bank 4l mod 32, and each
// 8-lane phase of an LDS.128 covers all 32 banks exactly once.
__global__ void __launch_bounds__(256)
spline_eval_kernel(const float* __restrict__ x,
                   const float* __restrict__ knots,
                   const float* __restrict__ coeffs,
                   float* __restrict__ out,
                   int n)
{
    __shared__ float  s_k[NKNOTS];
    __shared__ float  s_y[NKNOTS];
    __shared__ float  s_h[NSEG];
    __shared__ float  s_delta[NSEG];
    __shared__ float  s_d[NKNOTS];
    __shared__ float4 s_c[NSEG];
    __shared__ float4 s_crep[NSEG][32];   // replicated, conflict-free
    __shared__ float  s_scal[3];          // k0, kN, invH

    const int tid  = threadIdx.x;
    const int lane = tid & 31;

    // ---- tiny PCHIP prep, redundantly per block ----
    if (tid < NKNOTS) {
        s_k[tid] = knots[tid];
        s_y[tid] = coeffs[tid];
    }
    __syncthreads();
    if (tid < NSEG) {
        float h = s_k[tid + 1] - s_k[tid];
        s_h[tid]     = h;
        s_delta[tid] = (s_y[tid + 1] - s_y[tid]) / (h + SPL_EPS);
    }
    __syncthreads();
    if (tid < NKNOTS) {
        float d;
        if (tid == 0) {
            float h0 = s_h[0], h1 = s_h[1];
            float de0 = s_delta[0], de1 = s_delta[1];
            d = ((2.0f * h0 + h1) * de0 - h0 * de1) / (h0 + h1 + SPL_EPS);
            if (d * de0 <= 0.0f)                 d = 0.0f;
            else if (fabsf(d) > 3.0f * fabsf(de0)) d = 3.0f * de0;
        } else if (tid == NKNOTS - 1) {
            float hl = s_h[NSEG - 1], hp = s_h[NSEG - 2];
            float del = s_delta[NSEG - 1], dep = s_delta[NSEG - 2];
            d = ((2.0f * hl + hp) * del - hl * dep) / (hl + hp + SPL_EPS);
            if (d * del <= 0.0f)                 d = 0.0f;
            else if (fabsf(d) > 3.0f * fabsf(del)) d = 3.0f * del;
        } else {
            float hkm1 = s_h[tid - 1], hk = s_h[tid];
            float dm = s_delta[tid - 1], dp = s_delta[tid];
            float w1 = 2.0f * hk + hkm1;
            float w2 = hk + 2.0f * hkm1;
            float dint = (w1 + w2) / (w1 / (dm + SPL_EPS) + w2 / (dp + SPL_EPS));
            d = (dm * dp > 0.0f) ? dint : 0.0f;
        }
        s_d[tid] = d;
    }
    __syncthreads();
    if (tid < NSEG) {
        float h      = s_h[tid];
        float safe_h = (fabsf(h) < SPL_EPS) ? 1.0f : h;
        float yk  = s_y[tid], yk1 = s_y[tid + 1];
        float hd0 = safe_h * s_d[tid];
        float hd1 = safe_h * s_d[tid + 1];
        float4 c;
        c.x = yk;
        c.y = hd0;
        c.z = -3.0f * yk - 2.0f * hd0 + 3.0f * yk1 - hd1;
        c.w =  2.0f * yk +        hd0 - 2.0f * yk1 + hd1;
        s_c[tid] = c;
    }
    if (tid == 0) {
        float k0 = s_k[0];
        float kN = s_k[NKNOTS - 1];
        s_scal[0] = k0;
        s_scal[1] = kN;
        // knots are linspace -> uniform segment width.
        s_scal[2] = (float)(NKNOTS - 1) / (kN - k0);
    }
    __syncthreads();

    // Replicate the coefficient table across the 32 lane slots.
    for (int i = tid; i < NSEG * 32; i += blockDim.x) {
        s_crep[i >> 5][i & 31] = s_c[i >> 5];
    }
    __syncthreads();

    const float k0   = s_scal[0];
    const float kN   = s_scal[1];
    const float invH = s_scal[2];
    const float4* __restrict__ lut = &s_crep[0][lane];  // stride 32 float4s

    auto eval1 = [&](float xv) -> float {
        float xc = fminf(fmaxf(xv, k0), kN);
        float s  = (xc - k0) * invH;
        int idx  = (int)s;
        idx = idx < 0 ? 0 : (idx > NSEG - 1 ? NSEG - 1 : idx);
        float t  = s - (float)idx;
        float4 c = lut[idx << 5];   // conflict-free LDS.128
        return fmaf(t, fmaf(t, fmaf(t, c.w, c.z), c.y), c.x);
    };
    auto eval4 = [&](float4 xv) -> float4 {
        float4 yv;
        yv.x = eval1(xv.x);
        yv.y = eval1(xv.y);
        yv.z = eval1(xv.z);
        yv.w = eval1(xv.w);
        return yv;
    };

    // ---- streaming evaluation, float4 vectorized grid-stride, 2x unrolled ----
    const int n4  = n >> 2;
    const int gsz = gridDim.x * blockDim.x;
    const float4* __restrict__ x4 = (const float4*)x;
    float4* __restrict__ o4 = (float4*)out;

    int i = blockIdx.x * blockDim.x + tid;
    for (; i + gsz < n4; i += 2 * gsz) {
        float4 a = x4[i];
        float4 b = x4[i + gsz];
        float4 ya = eval4(a);
        float4 yb = eval4(b);
        o4[i]       = ya;
        o4[i + gsz] = yb;
    }
    for (; i < n4; i += gsz) {
        o4[i] = eval4(x4[i]);
    }
    // scalar tail (n not divisible by 4)
    for (int j = (n4 << 2) + blockIdx.x * blockDim.x + tid; j < n; j += gsz) {
        out[j] = eval1(x[j]);
    }
}

extern "C" void kernel_launch(void* const* d_in, const int* in_sizes, int n_in,
                              void* d_out, int out_size)
{
    const float* x      = (const float*)d_in[0];
    const float* knots  = (const float*)d_in[1];
    const float* coeffs = (const float*)d_in[2];
    float* out          = (float*)d_out;
    const int n         = in_sizes[0];

    const int threads = 256;
    int blocks = 148 * 8;
    int work4  = (n >> 2);
    if (work4 > 0) {
        int need = (work4 + threads - 1) / threads;
        if (blocks > need) blocks = need;
    }
    if (blocks < 1) blocks = 1;

    spline_eval_kernel<<<blocks, threads>>>(x, knots, coeffs, out, n);
}

// round 8
// speedup vs baseline: 1.1164x; 1.0361x over previous
#include <cuda_runtime.h>
#include <cuda_bf16.h>

#define SPL_EPS 1e-12f
#define NKNOTS 30
#define NSEG   29

// PCHIP spline, uniform knots. Per segment: y = c0 + t*(c1 + t*(c2 + t*c3)).
// The 29 segments' float4 coefficients are replicated per-lane in shared memory
// (s_crep[seg][lane]) so the per-element LDS.128 gather is bank-conflict-free
// for ANY index pattern. __launch_bounds__(256,8) pins 8 CTAs/SM so the
// 148*8-block grid is exactly one wave (no serial tail).
__global__ void __launch_bounds__(256, 8)
spline_eval_kernel(const float* __restrict__ x,
                   const float* __restrict__ knots,
                   const float* __restrict__ coeffs,
                   float* __restrict__ out,
                   int n)
{
    __shared__ float  s_k[NKNOTS];
    __shared__ float  s_y[NKNOTS];
    __shared__ float  s_h[NSEG];
    __shared__ float  s_delta[NSEG];
    __shared__ float  s_d[NKNOTS];
    __shared__ float4 s_c[NSEG];
    __shared__ float4 s_crep[NSEG][32];   // replicated, conflict-free
    __shared__ float  s_scal[3];          // k0, kN, invH

    const int tid  = threadIdx.x;
    const int lane = tid & 31;

    // ---- tiny PCHIP prep, redundantly per block ----
    if (tid < NKNOTS) {
        s_k[tid] = knots[tid];
        s_y[tid] = coeffs[tid];
    }
    __syncthreads();
    if (tid < NSEG) {
        float h = s_k[tid + 1] - s_k[tid];
        s_h[tid]     = h;
        s_delta[tid] = (s_y[tid + 1] - s_y[tid]) / (h + SPL_EPS);
    }
    __syncthreads();
    if (tid < NKNOTS) {
        float d;
        if (tid == 0) {
            float h0 = s_h[0], h1 = s_h[1];
            float de0 = s_delta[0], de1 = s_delta[1];
            d = ((2.0f * h0 + h1) * de0 - h0 * de1) / (h0 + h1 + SPL_EPS);
            if (d * de0 <= 0.0f)                 d = 0.0f;
            else if (fabsf(d) > 3.0f * fabsf(de0)) d = 3.0f * de0;
        } else if (tid == NKNOTS - 1) {
            float hl = s_h[NSEG - 1], hp = s_h[NSEG - 2];
            float del = s_delta[NSEG - 1], dep = s_delta[NSEG - 2];
            d = ((2.0f * hl + hp) * del - hl * dep) / (hl + hp + SPL_EPS);
            if (d * del <= 0.0f)                 d = 0.0f;
            else if (fabsf(d) > 3.0f * fabsf(del)) d = 3.0f * del;
        } else {
            float hkm1 = s_h[tid - 1], hk = s_h[tid];
            float dm = s_delta[tid - 1], dp = s_delta[tid];
            float w1 = 2.0f * hk + hkm1;
            float w2 = hk + 2.0f * hkm1;
            float dint = (w1 + w2) / (w1 / (dm + SPL_EPS) + w2 / (dp + SPL_EPS));
            d = (dm * dp > 0.0f) ? dint : 0.0f;
        }
        s_d[tid] = d;
    }
    __syncthreads();
    if (tid < NSEG) {
        float h      = s_h[tid];
        float safe_h = (fabsf(h) < SPL_EPS) ? 1.0f : h;
        float yk  = s_y[tid], yk1 = s_y[tid + 1];
        float hd0 = safe_h * s_d[tid];
        float hd1 = safe_h * s_d[tid + 1];
        float4 c;
        c.x = yk;
        c.y = hd0;
        c.z = -3.0f * yk - 2.0f * hd0 + 3.0f * yk1 - hd1;
        c.w =  2.0f * yk +        hd0 - 2.0f * yk1 + hd1;
        s_c[tid] = c;
    }
    if (tid == 0) {
        float k0 = s_k[0];
        float kN = s_k[NKNOTS - 1];
        s_scal[0] = k0;
        s_scal[1] = kN;
        // knots are linspace -> uniform segment width.
        s_scal[2] = (float)(NKNOTS - 1) / (kN - k0);
    }
    __syncthreads();

    // Replicate the coefficient table across the 32 lane slots.
    for (int i = tid; i < NSEG * 32; i += blockDim.x) {
        s_crep[i >> 5][i & 31] = s_c[i >> 5];
    }
    __syncthreads();

    const float k0   = s_scal[0];
    const float kN   = s_scal[1];
    const float invH = s_scal[2];
    const float4* __restrict__ lut = &s_crep[0][lane];  // stride 32 float4s

    auto eval1 = [&](float xv) -> float {
        float xc = fminf(fmaxf(xv, k0), kN);
        float s  = (xc - k0) * invH;
        int idx  = (int)s;
        idx = idx < 0 ? 0 : (idx > NSEG - 1 ? NSEG - 1 : idx);
        float t  = s - (float)idx;
        float4 c = lut[idx << 5];   // conflict-free LDS.128
        return fmaf(t, fmaf(t, fmaf(t, c.w, c.z), c.y), c.x);
    };
    auto eval4 = [&](float4 xv) -> float4 {
        float4 yv;
        yv.x = eval1(xv.x);
        yv.y = eval1(xv.y);
        yv.z = eval1(xv.z);
        yv.w = eval1(xv.w);
        return yv;
    };

    // ---- streaming evaluation, float4 vectorized grid-stride ----
    // 2x unrolled loads (MLP), but compute+store a before computing b to keep
    // live register state inside the 32-reg / 8-CTA budget.
    const int n4  = n >> 2;
    const int gsz = gridDim.x * blockDim.x;
    const float4* __restrict__ x4 = (const float4*)x;
    float4* __restrict__ o4 = (float4*)out;

    int i = blockIdx.x * blockDim.x + tid;
    for (; i + gsz < n4; i += 2 * gsz) {
        float4 a = x4[i];
        float4 b = x4[i + gsz];
        o4[i]       = eval4(a);
        o4[i + gsz] = eval4(b);
    }
    for (; i < n4; i += gsz) {
        o4[i] = eval4(x4[i]);
    }
    // scalar tail (n not divisible by 4)
    for (int j = (n4 << 2) + blockIdx.x * blockDim.x + tid; j < n; j += gsz) {
        out[j] = eval1(x[j]);
    }
}

extern "C" void kernel_launch(void* const* d_in, const int* in_sizes, int n_in,
                              void* d_out, int out_size)
{
    const float* x      = (const float*)d_in[0];
    const float* knots  = (const float*)d_in[1];
    const float* coeffs = (const float*)d_in[2];
    float* out          = (float*)d_out;
    const int n         = in_sizes[0];

    const int threads = 256;
    int blocks = 148 * 8;   // exactly one wave at 8 CTAs/SM
    int work4  = (n >> 2);
    if (work4 > 0) {
        int need = (work4 + threads - 1) / threads;
        if (blocks > need) blocks = need;
    }
    if (blocks < 1) blocks = 1;

    spline_eval_kernel<<<blocks, threads>>>(x, knots, coeffs, out, n);
}